// round 1
// baseline (speedup 1.0000x reference)
#include <cuda_runtime.h>
#include <cstdint>

#define NODES 32768
#define KNB   12
#define DIM   128

// scratch for the attention-aggregated vectors (16.8 MB, static — no allocs)
__device__ float g_agg[NODES * DIM];

// ---------------------------------------------------------------------------
// Kernel 1: per-node attention + weighted neighbor aggregation.
// Block = 128 threads = 4 warps = 4 nodes (one warp per node).
// Shared: w1 staged once per block (66 KB) + per-node feat tiles.
// Inner GEMM register-tiled: thread owns 4 output columns x 12 k-rows,
// accumulated with packed fma.rn.f32x2 (FFMA2).
// ---------------------------------------------------------------------------
extern "C" __global__ void __launch_bounds__(128, 2)
attn_agg_kernel(const float* __restrict__ nbr,
                const float* __restrict__ wgt,
                const float* __restrict__ extra,
                const float* __restrict__ w1,
                const float* __restrict__ w2)
{
    extern __shared__ float smem[];
    float* s_w1    = smem;                     // 129*128 floats
    float* s_feat  = s_w1 + 129 * DIM;         // 4*12*128
    float* s_extra = s_feat + 4 * KNB * DIM;   // 4*128
    float* s_wgt   = s_extra + 4 * DIM;        // 4*16

    const int t    = threadIdx.x;
    const int lane = t & 31;
    const int w    = t >> 5;
    const long node = (long)blockIdx.x * 4 + w;

    // ---- stage w1 (cooperative, float4 coalesced) ----
    const float4* w1g  = (const float4*)w1;
    float4*       s_w1v = (float4*)s_w1;
    #pragma unroll
    for (int i = 0; i < 33; ++i) {
        int idx = t + i * 128;                 // 129*32 = 4128 float4 total
        if (idx < 129 * 32) s_w1v[idx] = w1g[idx];
    }

    // ---- stage extra + edge weights (per warp) ----
    const float4* ev  = (const float4*)(extra + node * DIM);
    float4*       s_ev = (float4*)(s_extra + w * DIM);
    s_ev[lane] = ev[lane];
    if (lane < KNB) s_wgt[w * 16 + lane] = wgt[node * KNB + lane];
    __syncwarp();

    // ---- feat[k][f] = extra[f] * nbr[k][f] into shared ----
    const float4* nv   = (const float4*)(nbr + node * KNB * DIM);
    float4*       s_fv = (float4*)(s_feat + w * KNB * DIM);
    {
        float4 e4 = s_ev[lane];
        #pragma unroll
        for (int k = 0; k < KNB; ++k) {
            float4 n4 = nv[k * 32 + lane];
            float4 f4;
            f4.x = n4.x * e4.x; f4.y = n4.y * e4.y;
            f4.z = n4.z * e4.z; f4.w = n4.w * e4.w;
            s_fv[k * 32 + lane] = f4;
        }
    }
    __syncthreads();   // w1 staged by all threads

    // ---- alpha[k][4 cols] = feat[12,129] @ w1[129,128] (f32x2 packed) ----
    unsigned long long acc[KNB][2];
    #pragma unroll
    for (int k = 0; k < KNB; ++k) { acc[k][0] = 0ull; acc[k][1] = 0ull; }

    const ulonglong2* w1p = (const ulonglong2*)s_w1;   // 32 x 16B per row

    #pragma unroll 1
    for (int f4 = 0; f4 < 32; ++f4) {
        ulonglong2 wv0 = w1p[(f4 * 4 + 0) * 32 + lane];
        ulonglong2 wv1 = w1p[(f4 * 4 + 1) * 32 + lane];
        ulonglong2 wv2 = w1p[(f4 * 4 + 2) * 32 + lane];
        ulonglong2 wv3 = w1p[(f4 * 4 + 3) * 32 + lane];
        #pragma unroll
        for (int k = 0; k < KNB; ++k) {
            float4 fq = s_fv[k * 32 + f4];     // broadcast LDS.128
            unsigned long long d0, d1, d2, d3;
            asm("mov.b64 %0, {%1, %1};" : "=l"(d0) : "r"(__float_as_uint(fq.x)));
            asm("mov.b64 %0, {%1, %1};" : "=l"(d1) : "r"(__float_as_uint(fq.y)));
            asm("mov.b64 %0, {%1, %1};" : "=l"(d2) : "r"(__float_as_uint(fq.z)));
            asm("mov.b64 %0, {%1, %1};" : "=l"(d3) : "r"(__float_as_uint(fq.w)));
            asm("fma.rn.f32x2 %0, %1, %2, %0;" : "+l"(acc[k][0]) : "l"(d0), "l"(wv0.x));
            asm("fma.rn.f32x2 %0, %1, %2, %0;" : "+l"(acc[k][1]) : "l"(d0), "l"(wv0.y));
            asm("fma.rn.f32x2 %0, %1, %2, %0;" : "+l"(acc[k][0]) : "l"(d1), "l"(wv1.x));
            asm("fma.rn.f32x2 %0, %1, %2, %0;" : "+l"(acc[k][1]) : "l"(d1), "l"(wv1.y));
            asm("fma.rn.f32x2 %0, %1, %2, %0;" : "+l"(acc[k][0]) : "l"(d2), "l"(wv2.x));
            asm("fma.rn.f32x2 %0, %1, %2, %0;" : "+l"(acc[k][1]) : "l"(d2), "l"(wv2.y));
            asm("fma.rn.f32x2 %0, %1, %2, %0;" : "+l"(acc[k][0]) : "l"(d3), "l"(wv3.x));
            asm("fma.rn.f32x2 %0, %1, %2, %0;" : "+l"(acc[k][1]) : "l"(d3), "l"(wv3.y));
        }
    }
    // bias row f=128: + weight[k] * w1[128][c]
    {
        ulonglong2 wv = w1p[128 * 32 + lane];
        #pragma unroll
        for (int k = 0; k < KNB; ++k) {
            unsigned long long d;
            asm("mov.b64 %0, {%1, %1};" : "=l"(d) : "r"(__float_as_uint(s_wgt[w * 16 + k])));
            asm("fma.rn.f32x2 %0, %1, %2, %0;" : "+l"(acc[k][0]) : "l"(d), "l"(wv.x));
            asm("fma.rn.f32x2 %0, %1, %2, %0;" : "+l"(acc[k][1]) : "l"(d), "l"(wv.y));
        }
    }

    // ---- leaky_relu, project onto w2, warp-allreduce -> logits ----
    const float4 w2v = ((const float4*)w2)[lane];
    float logit[KNB];
    float m = -1e30f;
    #pragma unroll
    for (int k = 0; k < KNB; ++k) {
        unsigned long long v0 = acc[k][0], v1 = acc[k][1];
        float a0 = __uint_as_float((unsigned)v0);
        float a1 = __uint_as_float((unsigned)(v0 >> 32));
        float a2 = __uint_as_float((unsigned)v1);
        float a3 = __uint_as_float((unsigned)(v1 >> 32));
        a0 = (a0 >= 0.f) ? a0 : 0.2f * a0;
        a1 = (a1 >= 0.f) ? a1 : 0.2f * a1;
        a2 = (a2 >= 0.f) ? a2 : 0.2f * a2;
        a3 = (a3 >= 0.f) ? a3 : 0.2f * a3;
        float s = a0 * w2v.x + a1 * w2v.y + a2 * w2v.z + a3 * w2v.w;
        #pragma unroll
        for (int o = 16; o > 0; o >>= 1) s += __shfl_xor_sync(0xffffffffu, s, o);
        logit[k] = s;
        m = fmaxf(m, s);
    }

    // ---- softmax over K=12 (redundant per lane) ----
    float p[KNB];
    float sum = 0.f;
    #pragma unroll
    for (int k = 0; k < KNB; ++k) { p[k] = expf(logit[k] - m); sum += p[k]; }
    const float inv = 1.0f / sum;

    // ---- agg[c] = sum_k p[k] * nbr[k][c]  (nbr reload: L1/L2 hot) ----
    float4 agg = make_float4(0.f, 0.f, 0.f, 0.f);
    #pragma unroll
    for (int k = 0; k < KNB; ++k) {
        float4 n4 = nv[k * 32 + lane];
        float pk = p[k] * inv;
        agg.x += pk * n4.x; agg.y += pk * n4.y;
        agg.z += pk * n4.z; agg.w += pk * n4.w;
    }
    ((float4*)g_agg)[node * 32 + lane] = agg;
}

// ---------------------------------------------------------------------------
// Kernel 2: out = relu(concat(self, agg) @ w3), tiled GEMM.
// Block = 256 threads, tile = 64 rows x 128 cols, A-tile (64x256) in shared,
// w3 streamed from L1 (131 KB, resident). Thread tile = 8 rows x 4 cols.
// ---------------------------------------------------------------------------
extern "C" __global__ void __launch_bounds__(256, 2)
out_gemm_kernel(const float* __restrict__ selfv,
                const float* __restrict__ w3,
                float* __restrict__ out)
{
    extern __shared__ float s_A[];             // 64 * 256 floats
    const int t  = threadIdx.x;
    const int tx = t & 31;
    const int ty = t >> 5;
    const long r0 = (long)blockIdx.x * 64;

    const float4* sv  = (const float4*)(selfv + r0 * DIM);
    const float4* av  = (const float4*)(g_agg + r0 * DIM);
    float4*       sA4 = (float4*)s_A;
    #pragma unroll
    for (int i = 0; i < 16; ++i) {
        int idx = t + i * 256;                 // 4096 float4
        int row = idx >> 6;
        int c4  = idx & 63;
        sA4[row * 64 + c4] = (c4 < 32) ? sv[row * 32 + c4]
                                       : av[row * 32 + (c4 - 32)];
    }
    __syncthreads();

    unsigned long long acc[8][2];
    #pragma unroll
    for (int i = 0; i < 8; ++i) { acc[i][0] = 0ull; acc[i][1] = 0ull; }

    const ulonglong2* w3p = (const ulonglong2*)w3;   // 32 x 16B per row

    #pragma unroll 1
    for (int j4 = 0; j4 < 64; ++j4) {
        ulonglong2 wv0 = w3p[(j4 * 4 + 0) * 32 + tx];
        ulonglong2 wv1 = w3p[(j4 * 4 + 1) * 32 + tx];
        ulonglong2 wv2 = w3p[(j4 * 4 + 2) * 32 + tx];
        ulonglong2 wv3 = w3p[(j4 * 4 + 3) * 32 + tx];
        #pragma unroll
        for (int i = 0; i < 8; ++i) {
            float4 a4 = sA4[(ty * 8 + i) * 64 + j4];   // broadcast LDS.128
            unsigned long long d0, d1, d2, d3;
            asm("mov.b64 %0, {%1, %1};" : "=l"(d0) : "r"(__float_as_uint(a4.x)));
            asm("mov.b64 %0, {%1, %1};" : "=l"(d1) : "r"(__float_as_uint(a4.y)));
            asm("mov.b64 %0, {%1, %1};" : "=l"(d2) : "r"(__float_as_uint(a4.z)));
            asm("mov.b64 %0, {%1, %1};" : "=l"(d3) : "r"(__float_as_uint(a4.w)));
            asm("fma.rn.f32x2 %0, %1, %2, %0;" : "+l"(acc[i][0]) : "l"(d0), "l"(wv0.x));
            asm("fma.rn.f32x2 %0, %1, %2, %0;" : "+l"(acc[i][1]) : "l"(d0), "l"(wv0.y));
            asm("fma.rn.f32x2 %0, %1, %2, %0;" : "+l"(acc[i][0]) : "l"(d1), "l"(wv1.x));
            asm("fma.rn.f32x2 %0, %1, %2, %0;" : "+l"(acc[i][1]) : "l"(d1), "l"(wv1.y));
            asm("fma.rn.f32x2 %0, %1, %2, %0;" : "+l"(acc[i][0]) : "l"(d2), "l"(wv2.x));
            asm("fma.rn.f32x2 %0, %1, %2, %0;" : "+l"(acc[i][1]) : "l"(d2), "l"(wv2.y));
            asm("fma.rn.f32x2 %0, %1, %2, %0;" : "+l"(acc[i][0]) : "l"(d3), "l"(wv3.x));
            asm("fma.rn.f32x2 %0, %1, %2, %0;" : "+l"(acc[i][1]) : "l"(d3), "l"(wv3.y));
        }
    }

    #pragma unroll
    for (int i = 0; i < 8; ++i) {
        unsigned long long v0 = acc[i][0], v1 = acc[i][1];
        float4 o;
        o.x = fmaxf(__uint_as_float((unsigned)v0),         0.f);
        o.y = fmaxf(__uint_as_float((unsigned)(v0 >> 32)), 0.f);
        o.z = fmaxf(__uint_as_float((unsigned)v1),         0.f);
        o.w = fmaxf(__uint_as_float((unsigned)(v1 >> 32)), 0.f);
        ((float4*)out)[(r0 + ty * 8 + i) * 32 + tx] = o;
    }
}

// ---------------------------------------------------------------------------
extern "C" void kernel_launch(void* const* d_in, const int* in_sizes, int n_in,
                              void* d_out, int out_size)
{
    // metadata order: self, neighbor, [batch_size scalar], masks, neighbor_weight,
    //                 extra, w1, w2, w3
    int idx = 0;
    const float* selfv = (const float*)d_in[idx++];
    const float* nbr   = (const float*)d_in[idx++];
    if (idx < n_in && in_sizes[idx] == 1) idx++;   // batch_size (scalar, unused)
    idx++;                                         // masks (unused by reference)
    const float* wgt   = (const float*)d_in[idx++];
    const float* extra = (const float*)d_in[idx++];
    const float* w1    = (const float*)d_in[idx++];
    const float* w2    = (const float*)d_in[idx++];
    const float* w3    = (const float*)d_in[idx++];
    float* out = (float*)d_out;

    const int smem1 = (129 * DIM + 4 * KNB * DIM + 4 * DIM + 4 * 16) * sizeof(float); // 92928
    const int smem2 = 64 * 256 * sizeof(float);                                       // 65536

    cudaFuncSetAttribute(attn_agg_kernel, cudaFuncAttributeMaxDynamicSharedMemorySize, smem1);
    cudaFuncSetAttribute(out_gemm_kernel, cudaFuncAttributeMaxDynamicSharedMemorySize, smem2);

    attn_agg_kernel<<<NODES / 4, 128, smem1>>>(nbr, wgt, extra, w1, w2);
    out_gemm_kernel<<<NODES / 64, 256, smem2>>>(selfv, w3, out);
    (void)out_size; (void)n_in;
}

// round 3
// speedup vs baseline: 1.3521x; 1.3521x over previous
#include <cuda_runtime.h>
#include <cstdint>

#define NODES 32768
#define KNB   12
#define DIM   128
#define ROWS  (NODES * KNB)          // 393216
#define NSUP  (ROWS / 128)           // 3072 row-tiles of 128
#define GRID1 152

__device__ float g_agg[NODES * DIM];
__device__ float g_logits[ROWS];

__device__ __forceinline__ uint32_t smem_u32(const void* p) {
    uint32_t a;
    asm("{ .reg .u64 t; cvta.to.shared.u64 t, %1; cvt.u32.u64 %0, t; }"
        : "=r"(a) : "l"(p));
    return a;
}

#define LDSM4(r, addr) \
    asm volatile("ldmatrix.sync.aligned.m8n8.x4.shared.b16 {%0,%1,%2,%3}, [%4];" \
        : "=r"((r)[0]), "=r"((r)[1]), "=r"((r)[2]), "=r"((r)[3]) : "r"(addr))

#define MMA(acc, a, b) \
    asm volatile("mma.sync.aligned.m16n8k16.row.col.f32.bf16.bf16.f32 " \
        "{%0,%1,%2,%3}, {%4,%5,%6,%7}, {%8,%9}, {%0,%1,%2,%3};" \
        : "+f"((acc)[0]), "+f"((acc)[1]), "+f"((acc)[2]), "+f"((acc)[3]) \
        : "r"((a)[0]), "r"((a)[1]), "r"((a)[2]), "r"((a)[3]), \
          "r"((b)[0]), "r"((b)[1]))

// SMEM layout (bytes). Tiles are [row][k] bf16, 256B rows, 16B-chunk XOR swizzle.
#define SM_WHI  0
#define SM_WLO  32768
#define SM_AHI  65536
#define SM_ALO  98304
#define SM_MISC 131072             // w1 bias row [128] f32 | w2 [128] f32
#define SMEM1   (SM_MISC + 1024)

__device__ __forceinline__ uint32_t sw_off(int row, int chunk) {
    return (uint32_t)(row * 256 + ((chunk ^ (row & 7)) << 4));
}

// ---------------------------------------------------------------------------
// K1: logits = LeakyReLU(feat @ w1[0:128] + wgt*w1[128]) @ w2
// bf16 hi/lo 3-pass via mma.sync (legacy HMMA path; tcgen05 PTX is sm_103a-
// gated and the harness compiles for plain sm_103).
// ---------------------------------------------------------------------------
extern "C" __global__ void __launch_bounds__(256, 1)
logits_kernel(const float* __restrict__ nbr,
              const float* __restrict__ wgt,
              const float* __restrict__ extra,
              const float* __restrict__ w1,
              const float* __restrict__ w2)
{
    extern __shared__ __align__(1024) char smem[];
    const int t    = threadIdx.x;
    const int lane = t & 31;
    const int w    = t >> 5;
    const uint32_t sb = smem_u32(smem);

    float* s_w1b = (float*)(smem + SM_MISC);
    float* s_w2  = s_w1b + 128;

    // ---- stage w1^T (Wt[n][k]) as bf16 hi/lo, swizzled (once) ----
    #pragma unroll 4
    for (int i = 0; i < 64; ++i) {
        int idx = t + i * 256;                 // 16384 = 128*128
        int n = idx >> 7, k = idx & 127;
        float x = w1[k * 128 + n];
        uint16_t hx, lx;
        asm("cvt.rn.bf16.f32 %0, %1;" : "=h"(hx) : "f"(x));
        float hf = __uint_as_float(((uint32_t)hx) << 16);
        asm("cvt.rn.bf16.f32 %0, %1;" : "=h"(lx) : "f"(x - hf));
        uint32_t off = sw_off(n, k >> 3) + (k & 7) * 2;
        asm volatile("st.shared.u16 [%0], %1;" :: "r"(sb + SM_WHI + off), "h"(hx));
        asm volatile("st.shared.u16 [%0], %1;" :: "r"(sb + SM_WLO + off), "h"(lx));
    }
    if (t < 128) { s_w1b[t] = w1[128 * 128 + t]; s_w2[t] = w2[t]; }
    __syncthreads();

    // per-lane ldmatrix address components
    const int aRow = (w << 4) + (lane & 15);
    const int aCb  = lane >> 4;
    const int aXor = aRow & 7;
    const uint32_t aHiBase = sb + SM_AHI + aRow * 256;
    const uint32_t aLoBase = sb + SM_ALO + aRow * 256;

    const int bNl = ((lane >> 4) << 3) + (lane & 7);   // n within 16-block
    const int bCb = (lane >> 3) & 1;

    const float4* nbr4   = (const float4*)nbr;
    const float4* extra4 = (const float4*)extra;

    for (int sup = blockIdx.x; sup < NSUP; sup += GRID1) {
        const int row0 = sup * 128;

        // ---- load nbr rows, fuse extra, bf16 hi/lo split into swizzled smem ----
        #pragma unroll 4
        for (int i = 0; i < 16; ++i) {
            int idx  = t + i * 256;            // 4096 float4 = 128 rows x 32
            int row  = idx >> 5;
            int c4   = idx & 31;
            unsigned grow = (unsigned)(row0 + row);
            unsigned node = grow / KNB;
            float4 n = nbr4[(size_t)grow * 32 + c4];
            float4 e = extra4[(size_t)node * 32 + c4];
            float x0 = n.x * e.x, x1 = n.y * e.y, x2 = n.z * e.z, x3 = n.w * e.w;
            uint32_t h01, h23, l01, l23;
            asm("cvt.rn.bf16x2.f32 %0, %1, %2;" : "=r"(h01) : "f"(x1), "f"(x0));
            asm("cvt.rn.bf16x2.f32 %0, %1, %2;" : "=r"(h23) : "f"(x3), "f"(x2));
            float hf0 = __uint_as_float(h01 << 16);
            float hf1 = __uint_as_float(h01 & 0xffff0000u);
            float hf2 = __uint_as_float(h23 << 16);
            float hf3 = __uint_as_float(h23 & 0xffff0000u);
            asm("cvt.rn.bf16x2.f32 %0, %1, %2;" : "=r"(l01) : "f"(x1 - hf1), "f"(x0 - hf0));
            asm("cvt.rn.bf16x2.f32 %0, %1, %2;" : "=r"(l23) : "f"(x3 - hf3), "f"(x2 - hf2));
            uint32_t off = sw_off(row, c4 >> 1) + (c4 & 1) * 8;
            asm volatile("st.shared.v2.b32 [%0], {%1,%2};"
                         :: "r"(sb + SM_AHI + off), "r"(h01), "r"(h23));
            asm volatile("st.shared.v2.b32 [%0], {%1,%2};"
                         :: "r"(sb + SM_ALO + off), "r"(l01), "r"(l23));
        }
        __syncthreads();

        // ---- warp GEMM: 16 rows x 128 cols, K=128, 3 passes ----
        float acc[16][4];
        #pragma unroll
        for (int nt = 0; nt < 16; ++nt)
            { acc[nt][0] = acc[nt][1] = acc[nt][2] = acc[nt][3] = 0.f; }

        #pragma unroll
        for (int ks = 0; ks < 8; ++ks) {
            uint32_t ah[4], al[4];
            uint32_t aoff = (uint32_t)(((2 * ks + aCb) ^ aXor) << 4);
            LDSM4(ah, aHiBase + aoff);
            LDSM4(al, aLoBase + aoff);

            uint32_t bh[16][2], bl[16][2];
            #pragma unroll
            for (int j = 0; j < 8; ++j) {
                int n = j * 16 + bNl;
                uint32_t off = (uint32_t)(n * 256 + (((2 * ks + bCb) ^ (n & 7)) << 4));
                uint32_t r[4];
                LDSM4(r, sb + SM_WHI + off);
                bh[2*j][0] = r[0]; bh[2*j][1] = r[1];
                bh[2*j+1][0] = r[2]; bh[2*j+1][1] = r[3];
                LDSM4(r, sb + SM_WLO + off);
                bl[2*j][0] = r[0]; bl[2*j][1] = r[1];
                bl[2*j+1][0] = r[2]; bl[2*j+1][1] = r[3];
            }
            #pragma unroll
            for (int nt = 0; nt < 16; ++nt) {
                MMA(acc[nt], ah, bh[nt]);
                MMA(acc[nt], ah, bl[nt]);
                MMA(acc[nt], al, bh[nt]);
            }
        }

        // ---- epilogue: bias + leaky_relu + dot(w2) + quad reduce ----
        {
            const int grp = lane >> 2, qid = lane & 3;
            const int r0g = row0 + (w << 4) + grp;
            const int r1g = r0g + 8;
            const float wr0 = __ldg(&wgt[r0g]);
            const float wr1 = __ldg(&wgt[r1g]);
            float lg0 = 0.f, lg1 = 0.f;
            #pragma unroll
            for (int nt = 0; nt < 16; ++nt) {
                int c0 = nt * 8 + qid * 2;
                float b0 = s_w1b[c0],     b1 = s_w1b[c0 + 1];
                float u0 = s_w2[c0],      u1 = s_w2[c0 + 1];
                float v;
                v = acc[nt][0] + wr0 * b0; v = (v >= 0.f) ? v : 0.2f * v; lg0 += v * u0;
                v = acc[nt][1] + wr0 * b1; v = (v >= 0.f) ? v : 0.2f * v; lg0 += v * u1;
                v = acc[nt][2] + wr1 * b0; v = (v >= 0.f) ? v : 0.2f * v; lg1 += v * u0;
                v = acc[nt][3] + wr1 * b1; v = (v >= 0.f) ? v : 0.2f * v; lg1 += v * u1;
            }
            lg0 += __shfl_xor_sync(0xffffffffu, lg0, 1);
            lg0 += __shfl_xor_sync(0xffffffffu, lg0, 2);
            lg1 += __shfl_xor_sync(0xffffffffu, lg1, 1);
            lg1 += __shfl_xor_sync(0xffffffffu, lg1, 2);
            if (qid == 0) { g_logits[r0g] = lg0; g_logits[r1g] = lg1; }
        }
        __syncthreads();
    }
}

// ---------------------------------------------------------------------------
// K2: softmax over K + weighted aggregation (memory bound)
// ---------------------------------------------------------------------------
extern "C" __global__ void __launch_bounds__(128, 8)
softmax_agg_kernel(const float* __restrict__ nbr)
{
    const int t = threadIdx.x, lane = t & 31, w = t >> 5;
    const long node = (long)blockIdx.x * 4 + w;

    float lg[KNB];
    float m = -1e30f;
    #pragma unroll
    for (int k = 0; k < KNB; ++k) { lg[k] = g_logits[node * KNB + k]; m = fmaxf(m, lg[k]); }
    float sum = 0.f;
    #pragma unroll
    for (int k = 0; k < KNB; ++k) { lg[k] = expf(lg[k] - m); sum += lg[k]; }
    const float inv = 1.0f / sum;

    const float4* nv = (const float4*)(nbr + node * KNB * DIM);
    float4 agg = make_float4(0.f, 0.f, 0.f, 0.f);
    #pragma unroll
    for (int k = 0; k < KNB; ++k) {
        float4 n4 = nv[k * 32 + lane];
        float pk = lg[k] * inv;
        agg.x += pk * n4.x; agg.y += pk * n4.y;
        agg.z += pk * n4.z; agg.w += pk * n4.w;
    }
    ((float4*)g_agg)[node * 32 + lane] = agg;
}

// ---------------------------------------------------------------------------
// K3: out = relu(concat(self, agg) @ w3)  (round-1 FFMA2 version)
// ---------------------------------------------------------------------------
extern "C" __global__ void __launch_bounds__(256, 2)
out_gemm_kernel(const float* __restrict__ selfv,
                const float* __restrict__ w3,
                float* __restrict__ out)
{
    extern __shared__ float s_A[];             // 64 * 256 floats
    const int t  = threadIdx.x;
    const int tx = t & 31;
    const int ty = t >> 5;
    const long r0 = (long)blockIdx.x * 64;

    const float4* sv  = (const float4*)(selfv + r0 * DIM);
    const float4* av  = (const float4*)(g_agg + r0 * DIM);
    float4*       sA4 = (float4*)s_A;
    #pragma unroll
    for (int i = 0; i < 16; ++i) {
        int idx = t + i * 256;
        int row = idx >> 6;
        int c4  = idx & 63;
        sA4[row * 64 + c4] = (c4 < 32) ? sv[row * 32 + c4]
                                       : av[row * 32 + (c4 - 32)];
    }
    __syncthreads();

    unsigned long long acc[8][2];
    #pragma unroll
    for (int i = 0; i < 8; ++i) { acc[i][0] = 0ull; acc[i][1] = 0ull; }

    const ulonglong2* w3p = (const ulonglong2*)w3;

    #pragma unroll 1
    for (int j4 = 0; j4 < 64; ++j4) {
        ulonglong2 wv0 = w3p[(j4 * 4 + 0) * 32 + tx];
        ulonglong2 wv1 = w3p[(j4 * 4 + 1) * 32 + tx];
        ulonglong2 wv2 = w3p[(j4 * 4 + 2) * 32 + tx];
        ulonglong2 wv3 = w3p[(j4 * 4 + 3) * 32 + tx];
        #pragma unroll
        for (int i = 0; i < 8; ++i) {
            float4 a4 = sA4[(ty * 8 + i) * 64 + j4];
            unsigned long long d0, d1, d2, d3;
            asm("mov.b64 %0, {%1, %1};" : "=l"(d0) : "r"(__float_as_uint(a4.x)));
            asm("mov.b64 %0, {%1, %1};" : "=l"(d1) : "r"(__float_as_uint(a4.y)));
            asm("mov.b64 %0, {%1, %1};" : "=l"(d2) : "r"(__float_as_uint(a4.z)));
            asm("mov.b64 %0, {%1, %1};" : "=l"(d3) : "r"(__float_as_uint(a4.w)));
            asm("fma.rn.f32x2 %0, %1, %2, %0;" : "+l"(acc[i][0]) : "l"(d0), "l"(wv0.x));
            asm("fma.rn.f32x2 %0, %1, %2, %0;" : "+l"(acc[i][1]) : "l"(d0), "l"(wv0.y));
            asm("fma.rn.f32x2 %0, %1, %2, %0;" : "+l"(acc[i][0]) : "l"(d1), "l"(wv1.x));
            asm("fma.rn.f32x2 %0, %1, %2, %0;" : "+l"(acc[i][1]) : "l"(d1), "l"(wv1.y));
            asm("fma.rn.f32x2 %0, %1, %2, %0;" : "+l"(acc[i][0]) : "l"(d2), "l"(wv2.x));
            asm("fma.rn.f32x2 %0, %1, %2, %0;" : "+l"(acc[i][1]) : "l"(d2), "l"(wv2.y));
            asm("fma.rn.f32x2 %0, %1, %2, %0;" : "+l"(acc[i][0]) : "l"(d3), "l"(wv3.x));
            asm("fma.rn.f32x2 %0, %1, %2, %0;" : "+l"(acc[i][1]) : "l"(d3), "l"(wv3.y));
        }
    }

    #pragma unroll
    for (int i = 0; i < 8; ++i) {
        unsigned long long v0 = acc[i][0], v1 = acc[i][1];
        float4 o;
        o.x = fmaxf(__uint_as_float((unsigned)v0),         0.f);
        o.y = fmaxf(__uint_as_float((unsigned)(v0 >> 32)), 0.f);
        o.z = fmaxf(__uint_as_float((unsigned)v1),         0.f);
        o.w = fmaxf(__uint_as_float((unsigned)(v1 >> 32)), 0.f);
        ((float4*)out)[(r0 + ty * 8 + i) * 32 + tx] = o;
    }
}

// ---------------------------------------------------------------------------
extern "C" void kernel_launch(void* const* d_in, const int* in_sizes, int n_in,
                              void* d_out, int out_size)
{
    int idx = 0;
    const float* selfv = (const float*)d_in[idx++];
    const float* nbr   = (const float*)d_in[idx++];
    if (idx < n_in && in_sizes[idx] == 1) idx++;   // batch_size scalar
    idx++;                                         // masks (unused)
    const float* wgt   = (const float*)d_in[idx++];
    const float* extra = (const float*)d_in[idx++];
    const float* w1    = (const float*)d_in[idx++];
    const float* w2    = (const float*)d_in[idx++];
    const float* w3    = (const float*)d_in[idx++];
    float* out = (float*)d_out;

    cudaFuncSetAttribute(logits_kernel,  cudaFuncAttributeMaxDynamicSharedMemorySize, SMEM1);
    cudaFuncSetAttribute(out_gemm_kernel, cudaFuncAttributeMaxDynamicSharedMemorySize, 65536);

    logits_kernel<<<GRID1, 256, SMEM1>>>(nbr, wgt, extra, w1, w2);
    softmax_agg_kernel<<<NODES / 4, 128>>>(nbr);
    out_gemm_kernel<<<NODES / 64, 256, 65536>>>(selfv, w3, out);
    (void)out_size; (void)n_in;
}

// round 4
// speedup vs baseline: 1.8342x; 1.3565x over previous
#include <cuda_runtime.h>
#include <cstdint>

#define NODES 32768
#define KNB   12
#define DIM   128
#define ROWS  (NODES * KNB)          // 393216
#define NSUP  (ROWS / 128)           // 3072 row-tiles of 128
#define GRID1 152

__device__ float g_agg[NODES * DIM];
__device__ float g_logits[ROWS];

__device__ __forceinline__ uint32_t smem_u32(const void* p) {
    uint32_t a;
    asm("{ .reg .u64 t; cvta.to.shared.u64 t, %1; cvt.u32.u64 %0, t; }"
        : "=r"(a) : "l"(p));
    return a;
}

#define LDSM4(r, addr) \
    asm volatile("ldmatrix.sync.aligned.m8n8.x4.shared.b16 {%0,%1,%2,%3}, [%4];" \
        : "=r"((r)[0]), "=r"((r)[1]), "=r"((r)[2]), "=r"((r)[3]) : "r"(addr))

#define MMA(acc, a, b) \
    asm volatile("mma.sync.aligned.m16n8k16.row.col.f32.bf16.bf16.f32 " \
        "{%0,%1,%2,%3}, {%4,%5,%6,%7}, {%8,%9}, {%0,%1,%2,%3};" \
        : "+f"((acc)[0]), "+f"((acc)[1]), "+f"((acc)[2]), "+f"((acc)[3]) \
        : "r"((a)[0]), "r"((a)[1]), "r"((a)[2]), "r"((a)[3]), \
          "r"((b)[0]), "r"((b)[1]))

#define BAR_SYNC(id)   asm volatile("bar.sync %0, 512;"   :: "r"(id) : "memory")
#define BAR_ARRIVE(id) asm volatile("bar.arrive %0, 512;" :: "r"(id) : "memory")

// bf16 hi/lo split of 4 floats -> packed bf16x2 pairs
__device__ __forceinline__ void split4(float x0, float x1, float x2, float x3,
                                       uint32_t& h01, uint32_t& h23,
                                       uint32_t& l01, uint32_t& l23) {
    asm("cvt.rn.bf16x2.f32 %0, %1, %2;" : "=r"(h01) : "f"(x1), "f"(x0));
    asm("cvt.rn.bf16x2.f32 %0, %1, %2;" : "=r"(h23) : "f"(x3), "f"(x2));
    float hf0 = __uint_as_float(h01 << 16);
    float hf1 = __uint_as_float(h01 & 0xffff0000u);
    float hf2 = __uint_as_float(h23 << 16);
    float hf3 = __uint_as_float(h23 & 0xffff0000u);
    asm("cvt.rn.bf16x2.f32 %0, %1, %2;" : "=r"(l01) : "f"(x1 - hf1), "f"(x0 - hf0));
    asm("cvt.rn.bf16x2.f32 %0, %1, %2;" : "=r"(l23) : "f"(x3 - hf3), "f"(x2 - hf2));
}

// ---------------------------------------------------------------------------
// K1 SMEM layout (bytes). A tiles: [row][k] bf16, 256B rows, 16B-chunk XOR sw.
#define SM_WHI   0
#define SM_WLO   32768
#define SM_A0HI  65536
#define SM_A0LO  98304
#define SM_A1HI  131072
#define SM_A1LO  163840
#define SM_MISC  196608            // w1 bias row [128] f32 | w2 [128] f32
#define SMEM1    (SM_MISC + 1024)

#define BAR_READY0 1
#define BAR_READY1 2
#define BAR_FREE0  3
#define BAR_FREE1  4

__device__ __forceinline__ uint32_t sw_off(int row, int chunk) {
    return (uint32_t)(row * 256 + ((chunk ^ (row & 7)) << 4));
}

// ---------------------------------------------------------------------------
// K1: logits = LeakyReLU(feat @ w1[0:128] + wgt*w1[128]) @ w2
// Warp-specialized: warps 0-7 MMA (bf16 hi/lo 3-pass), warps 8-15 produce
// converted tiles into double-buffered SMEM.
// ---------------------------------------------------------------------------
extern "C" __global__ void __launch_bounds__(512, 1)
logits_kernel(const float* __restrict__ nbr,
              const float* __restrict__ wgt,
              const float* __restrict__ extra,
              const float* __restrict__ w1,
              const float* __restrict__ w2)
{
    extern __shared__ __align__(1024) char smem[];
    const int t    = threadIdx.x;
    const int lane = t & 31;
    const int w    = t >> 5;
    const uint32_t sb = smem_u32(smem);

    float* s_w1b = (float*)(smem + SM_MISC);
    float* s_w2  = s_w1b + 128;

    // ---- stage w1^T (Wt[n][k]) as bf16 hi/lo, swizzled (once, all threads) ----
    #pragma unroll 4
    for (int i = 0; i < 32; ++i) {
        int idx = t + i * 512;                 // 16384 = 128*128
        int n = idx >> 7, k = idx & 127;
        float x = w1[k * 128 + n];
        uint16_t hx, lx;
        asm("cvt.rn.bf16.f32 %0, %1;" : "=h"(hx) : "f"(x));
        float hf = __uint_as_float(((uint32_t)hx) << 16);
        asm("cvt.rn.bf16.f32 %0, %1;" : "=h"(lx) : "f"(x - hf));
        uint32_t off = sw_off(n, k >> 3) + (k & 7) * 2;
        asm volatile("st.shared.u16 [%0], %1;" :: "r"(sb + SM_WHI + off), "h"(hx));
        asm volatile("st.shared.u16 [%0], %1;" :: "r"(sb + SM_WLO + off), "h"(lx));
    }
    if (t < 128) { s_w1b[t] = w1[128 * 128 + t]; s_w2[t] = w2[t]; }
    __syncthreads();

    if (w >= 8) {
        // ================= PRODUCER (warps 8-15) =================
        const int pt = t & 255;
        const float4* nbr4   = (const float4*)nbr;
        const float4* extra4 = (const float4*)extra;
        int it = 0;
        for (int sup = blockIdx.x; sup < NSUP; sup += GRID1, ++it) {
            const int b = it & 1;
            if (it >= 2) BAR_SYNC(b ? BAR_FREE1 : BAR_FREE0);
            const uint32_t aHi = sb + (b ? SM_A1HI : SM_A0HI);
            const uint32_t aLo = sb + (b ? SM_A1LO : SM_A0LO);
            const int row0 = sup * 128;
            #pragma unroll 4
            for (int i = 0; i < 16; ++i) {
                int idx  = pt + i * 256;       // 4096 float4 = 128 rows x 32
                int row  = idx >> 5;
                int c4   = idx & 31;
                unsigned grow = (unsigned)(row0 + row);
                unsigned node = grow / KNB;
                float4 n = nbr4[(size_t)grow * 32 + c4];
                float4 e = extra4[(size_t)node * 32 + c4];
                uint32_t h01, h23, l01, l23;
                split4(n.x * e.x, n.y * e.y, n.z * e.z, n.w * e.w, h01, h23, l01, l23);
                uint32_t off = sw_off(row, c4 >> 1) + (c4 & 1) * 8;
                asm volatile("st.shared.v2.b32 [%0], {%1,%2};"
                             :: "r"(aHi + off), "r"(h01), "r"(h23));
                asm volatile("st.shared.v2.b32 [%0], {%1,%2};"
                             :: "r"(aLo + off), "r"(l01), "r"(l23));
            }
            BAR_ARRIVE(b ? BAR_READY1 : BAR_READY0);
        }
    } else {
        // ================= CONSUMER (warps 0-7) =================
        const int aRow = (w << 4) + (lane & 15);
        const int aCb  = lane >> 4;
        const int aXor = aRow & 7;
        const int bNl  = ((lane >> 4) << 3) + (lane & 7);
        const int bCb  = (lane >> 3) & 1;

        int it = 0;
        for (int sup = blockIdx.x; sup < NSUP; sup += GRID1, ++it) {
            const int b = it & 1;
            BAR_SYNC(b ? BAR_READY1 : BAR_READY0);
            const uint32_t aHiBase = sb + (b ? SM_A1HI : SM_A0HI) + aRow * 256;
            const uint32_t aLoBase = sb + (b ? SM_A1LO : SM_A0LO) + aRow * 256;
            const int row0 = sup * 128;

            float acc[16][4];
            #pragma unroll
            for (int nt = 0; nt < 16; ++nt)
                { acc[nt][0] = acc[nt][1] = acc[nt][2] = acc[nt][3] = 0.f; }

            #pragma unroll
            for (int ks = 0; ks < 8; ++ks) {
                uint32_t ah[4], al[4];
                uint32_t aoff = (uint32_t)(((2 * ks + aCb) ^ aXor) << 4);
                LDSM4(ah, aHiBase + aoff);
                LDSM4(al, aLoBase + aoff);
                #pragma unroll
                for (int j = 0; j < 8; ++j) {
                    int n = j * 16 + bNl;
                    uint32_t off = (uint32_t)(n * 256 + (((2 * ks + bCb) ^ (n & 7)) << 4));
                    uint32_t rh[4], rl[4];
                    LDSM4(rh, sb + SM_WHI + off);
                    LDSM4(rl, sb + SM_WLO + off);
                    MMA(acc[2*j],   ah, rh);
                    MMA(acc[2*j],   ah, rl);
                    MMA(acc[2*j],   al, rh);
                    MMA(acc[2*j+1], ah, rh + 2);
                    MMA(acc[2*j+1], ah, rl + 2);
                    MMA(acc[2*j+1], al, rh + 2);
                }
            }
            BAR_ARRIVE(b ? BAR_FREE1 : BAR_FREE0);

            // ---- epilogue: bias + leaky_relu + dot(w2) + quad reduce ----
            const int grp = lane >> 2, qid = lane & 3;
            const int r0g = row0 + (w << 4) + grp;
            const int r1g = r0g + 8;
            const float wr0 = __ldg(&wgt[r0g]);
            const float wr1 = __ldg(&wgt[r1g]);
            float lg0 = 0.f, lg1 = 0.f;
            #pragma unroll
            for (int nt = 0; nt < 16; ++nt) {
                int c0 = nt * 8 + qid * 2;
                float b0 = s_w1b[c0], b1 = s_w1b[c0 + 1];
                float u0 = s_w2[c0],  u1 = s_w2[c0 + 1];
                float v;
                v = acc[nt][0] + wr0 * b0; v = (v >= 0.f) ? v : 0.2f * v; lg0 += v * u0;
                v = acc[nt][1] + wr0 * b1; v = (v >= 0.f) ? v : 0.2f * v; lg0 += v * u1;
                v = acc[nt][2] + wr1 * b0; v = (v >= 0.f) ? v : 0.2f * v; lg1 += v * u0;
                v = acc[nt][3] + wr1 * b1; v = (v >= 0.f) ? v : 0.2f * v; lg1 += v * u1;
            }
            lg0 += __shfl_xor_sync(0xffffffffu, lg0, 1);
            lg0 += __shfl_xor_sync(0xffffffffu, lg0, 2);
            lg1 += __shfl_xor_sync(0xffffffffu, lg1, 1);
            lg1 += __shfl_xor_sync(0xffffffffu, lg1, 2);
            if (qid == 0) { g_logits[r0g] = lg0; g_logits[r1g] = lg1; }
        }
    }
}

// ---------------------------------------------------------------------------
// K2: softmax over K + weighted aggregation (memory bound)
// ---------------------------------------------------------------------------
extern "C" __global__ void __launch_bounds__(128, 8)
softmax_agg_kernel(const float* __restrict__ nbr)
{
    const int t = threadIdx.x, lane = t & 31, w = t >> 5;
    const long node = (long)blockIdx.x * 4 + w;

    float lg[KNB];
    float m = -1e30f;
    #pragma unroll
    for (int k = 0; k < KNB; ++k) { lg[k] = g_logits[node * KNB + k]; m = fmaxf(m, lg[k]); }
    float sum = 0.f;
    #pragma unroll
    for (int k = 0; k < KNB; ++k) { lg[k] = expf(lg[k] - m); sum += lg[k]; }
    const float inv = 1.0f / sum;

    const float4* nv = (const float4*)(nbr + node * KNB * DIM);
    float4 agg = make_float4(0.f, 0.f, 0.f, 0.f);
    #pragma unroll
    for (int k = 0; k < KNB; ++k) {
        float4 n4 = nv[k * 32 + lane];
        float pk = lg[k] * inv;
        agg.x += pk * n4.x; agg.y += pk * n4.y;
        agg.z += pk * n4.z; agg.w += pk * n4.w;
    }
    ((float4*)g_agg)[node * 32 + lane] = agg;
}

// ---------------------------------------------------------------------------
// K3: out = relu(concat(self, agg) @ w3), bf16 hi/lo 3-pass mma.sync.
// Persistent grid 128 x 2 tiles; w3^T staged once (full K=256, hi/lo),
// A processed in two K-halves through one 64KB staging buffer.
// SMEM: W rows 512B (32 chunks), A rows 256B (16 chunks), XOR swizzle.
// ---------------------------------------------------------------------------
#define SM3_WHI 0
#define SM3_WLO 65536
#define SM3_AHI 131072
#define SM3_ALO 163840
#define SMEM3   196608
#define NT3     (NODES / 128)      // 256 tiles

extern "C" __global__ void __launch_bounds__(256, 1)
out_gemm_kernel(const float* __restrict__ selfv,
                const float* __restrict__ w3,
                float* __restrict__ out)
{
    extern __shared__ __align__(1024) char smem[];
    const int t    = threadIdx.x;
    const int lane = t & 31;
    const int w    = t >> 5;
    const uint32_t sb = smem_u32(smem);

    // ---- stage w3^T (Wt[n][k], k=0..255) hi/lo, swizzled (once) ----
    #pragma unroll 4
    for (int i = 0; i < 128; ++i) {
        int idx = t + i * 256;                 // 32768 = 256*128
        int n = idx >> 8, k = idx & 255;
        float x = w3[k * 128 + n];
        uint16_t hx, lx;
        asm("cvt.rn.bf16.f32 %0, %1;" : "=h"(hx) : "f"(x));
        float hf = __uint_as_float(((uint32_t)hx) << 16);
        asm("cvt.rn.bf16.f32 %0, %1;" : "=h"(lx) : "f"(x - hf));
        uint32_t off = (uint32_t)(n * 512 + (((k >> 3) ^ (n & 7)) << 4) + (k & 7) * 2);
        asm volatile("st.shared.u16 [%0], %1;" :: "r"(sb + SM3_WHI + off), "h"(hx));
        asm volatile("st.shared.u16 [%0], %1;" :: "r"(sb + SM3_WLO + off), "h"(lx));
    }

    const int aRow = (w << 4) + (lane & 15);
    const int aCb  = lane >> 4;
    const int aXor = aRow & 7;
    const int bNl  = ((lane >> 4) << 3) + (lane & 7);
    const int bCb  = (lane >> 3) & 1;
    const uint32_t aHiBase = sb + SM3_AHI + aRow * 256;
    const uint32_t aLoBase = sb + SM3_ALO + aRow * 256;

    for (int tile = blockIdx.x; tile < NT3; tile += 128) {
        const int r0 = tile * 128;

        float acc[16][4];
        #pragma unroll
        for (int nt = 0; nt < 16; ++nt)
            { acc[nt][0] = acc[nt][1] = acc[nt][2] = acc[nt][3] = 0.f; }

        #pragma unroll 1
        for (int half = 0; half < 2; ++half) {
            __syncthreads();       // previous MMA / W staging done
            // ---- fill A half: rows r0..r0+127, 128 cols fp32 -> hi/lo ----
            const float4* src = (const float4*)(half ? (const float*)g_agg : selfv);
            #pragma unroll 4
            for (int i = 0; i < 16; ++i) {
                int idx = t + i * 256;         // 4096 float4
                int row = idx >> 5;
                int c4  = idx & 31;
                float4 v = src[(size_t)(r0 + row) * 32 + c4];
                uint32_t h01, h23, l01, l23;
                split4(v.x, v.y, v.z, v.w, h01, h23, l01, l23);
                uint32_t off = sw_off(row, c4 >> 1) + (c4 & 1) * 8;
                asm volatile("st.shared.v2.b32 [%0], {%1,%2};"
                             :: "r"(sb + SM3_AHI + off), "r"(h01), "r"(h23));
                asm volatile("st.shared.v2.b32 [%0], {%1,%2};"
                             :: "r"(sb + SM3_ALO + off), "r"(l01), "r"(l23));
            }
            __syncthreads();

            #pragma unroll
            for (int ks = 0; ks < 8; ++ks) {
                uint32_t ah[4], al[4];
                uint32_t aoff = (uint32_t)(((2 * ks + aCb) ^ aXor) << 4);
                LDSM4(ah, aHiBase + aoff);
                LDSM4(al, aLoBase + aoff);
                const int kc = half * 16 + 2 * ks + bCb;
                #pragma unroll
                for (int j = 0; j < 8; ++j) {
                    int n = j * 16 + bNl;
                    uint32_t off = (uint32_t)(n * 512 + ((kc ^ (n & 7)) << 4));
                    uint32_t rh[4], rl[4];
                    LDSM4(rh, sb + SM3_WHI + off);
                    LDSM4(rl, sb + SM3_WLO + off);
                    MMA(acc[2*j],   ah, rh);
                    MMA(acc[2*j],   ah, rl);
                    MMA(acc[2*j],   al, rh);
                    MMA(acc[2*j+1], ah, rh + 2);
                    MMA(acc[2*j+1], ah, rl + 2);
                    MMA(acc[2*j+1], al, rh + 2);
                }
            }
        }

        // ---- relu + store ----
        const int grp = lane >> 2, qid = lane & 3;
        const int row0g = r0 + (w << 4) + grp;
        #pragma unroll
        for (int nt = 0; nt < 16; ++nt) {
            int col = nt * 8 + qid * 2;
            float2 o0, o1;
            o0.x = fmaxf(acc[nt][0], 0.f); o0.y = fmaxf(acc[nt][1], 0.f);
            o1.x = fmaxf(acc[nt][2], 0.f); o1.y = fmaxf(acc[nt][3], 0.f);
            *(float2*)(out + (size_t)row0g * 128 + col)       = o0;
            *(float2*)(out + (size_t)(row0g + 8) * 128 + col) = o1;
        }
    }
}

// ---------------------------------------------------------------------------
extern "C" void kernel_launch(void* const* d_in, const int* in_sizes, int n_in,
                              void* d_out, int out_size)
{
    int idx = 0;
    const float* selfv = (const float*)d_in[idx++];
    const float* nbr   = (const float*)d_in[idx++];
    if (idx < n_in && in_sizes[idx] == 1) idx++;   // batch_size scalar
    idx++;                                         // masks (unused)
    const float* wgt   = (const float*)d_in[idx++];
    const float* extra = (const float*)d_in[idx++];
    const float* w1    = (const float*)d_in[idx++];
    const float* w2    = (const float*)d_in[idx++];
    const float* w3    = (const float*)d_in[idx++];
    float* out = (float*)d_out;

    cudaFuncSetAttribute(logits_kernel,   cudaFuncAttributeMaxDynamicSharedMemorySize, SMEM1);
    cudaFuncSetAttribute(out_gemm_kernel, cudaFuncAttributeMaxDynamicSharedMemorySize, SMEM3);

    logits_kernel<<<GRID1, 512, SMEM1>>>(nbr, wgt, extra, w1, w2);
    softmax_agg_kernel<<<NODES / 4, 128>>>(nbr);
    out_gemm_kernel<<<128, 256, SMEM3>>>(selfv, w3, out);
    (void)out_size; (void)n_in;
}

// round 5
// speedup vs baseline: 2.0573x; 1.1217x over previous
#include <cuda_runtime.h>
#include <cuda_fp16.h>
#include <cstdint>

#define NODES 32768
#define KNB   12
#define DIM   128
#define ROWS  (NODES * KNB)          // 393216
#define NSUP  (ROWS / 128)           // 3072 row-tiles of 128
#define GRID1 152

__device__ float g_agg[NODES * DIM];
__device__ float g_logits[ROWS];

__device__ __forceinline__ uint32_t smem_u32(const void* p) {
    uint32_t a;
    asm("{ .reg .u64 t; cvta.to.shared.u64 t, %1; cvt.u32.u64 %0, t; }"
        : "=r"(a) : "l"(p));
    return a;
}

#define LDSM4(r, addr) \
    asm volatile("ldmatrix.sync.aligned.m8n8.x4.shared.b16 {%0,%1,%2,%3}, [%4];" \
        : "=r"((r)[0]), "=r"((r)[1]), "=r"((r)[2]), "=r"((r)[3]) : "r"(addr))

#define MMA_F16(acc, a, b) \
    asm volatile("mma.sync.aligned.m16n8k16.row.col.f32.f16.f16.f32 " \
        "{%0,%1,%2,%3}, {%4,%5,%6,%7}, {%8,%9}, {%0,%1,%2,%3};" \
        : "+f"((acc)[0]), "+f"((acc)[1]), "+f"((acc)[2]), "+f"((acc)[3]) \
        : "r"((a)[0]), "r"((a)[1]), "r"((a)[2]), "r"((a)[3]), \
          "r"((b)[0]), "r"((b)[1]))

#define MMA_BF16(acc, a, b) \
    asm volatile("mma.sync.aligned.m16n8k16.row.col.f32.bf16.bf16.f32 " \
        "{%0,%1,%2,%3}, {%4,%5,%6,%7}, {%8,%9}, {%0,%1,%2,%3};" \
        : "+f"((acc)[0]), "+f"((acc)[1]), "+f"((acc)[2]), "+f"((acc)[3]) \
        : "r"((a)[0]), "r"((a)[1]), "r"((a)[2]), "r"((a)[3]), \
          "r"((b)[0]), "r"((b)[1]))

#define BAR_SYNC(id)    asm volatile("bar.sync %0, 512;"   :: "r"(id) : "memory")
#define BAR_ARRIVE(id)  asm volatile("bar.arrive %0, 512;" :: "r"(id) : "memory")
#define BAR_SYNC_C(id)  asm volatile("bar.sync %0, 256;"   :: "r"(id) : "memory")

// bf16 hi/lo split of 4 floats (used by K3)
__device__ __forceinline__ void split4(float x0, float x1, float x2, float x3,
                                       uint32_t& h01, uint32_t& h23,
                                       uint32_t& l01, uint32_t& l23) {
    asm("cvt.rn.bf16x2.f32 %0, %1, %2;" : "=r"(h01) : "f"(x1), "f"(x0));
    asm("cvt.rn.bf16x2.f32 %0, %1, %2;" : "=r"(h23) : "f"(x3), "f"(x2));
    float hf0 = __uint_as_float(h01 << 16);
    float hf1 = __uint_as_float(h01 & 0xffff0000u);
    float hf2 = __uint_as_float(h23 << 16);
    float hf3 = __uint_as_float(h23 & 0xffff0000u);
    asm("cvt.rn.bf16x2.f32 %0, %1, %2;" : "=r"(l01) : "f"(x1 - hf1), "f"(x0 - hf0));
    asm("cvt.rn.bf16x2.f32 %0, %1, %2;" : "=r"(l23) : "f"(x3 - hf3), "f"(x2 - hf2));
}

__device__ __forceinline__ uint32_t sw_off(int row, int chunk) {
    return (uint32_t)(row * 256 + ((chunk ^ (row & 7)) << 4));
}

// ---------------------------------------------------------------------------
// K1 SMEM layout (bytes). fp16 tiles, 256B rows (128 fp16), 16B XOR swizzle.
#define SM_WHI   0                  // w1^T hi fp16  (32KB)
#define SM_WLO   32768              // w1^T lo fp16  (32KB)
#define SM_A0    65536              // feat fp16 buf0 (32KB)
#define SM_A1    98304
#define SM_A2    131072
#define SM_MISC  163840             // w1 bias [128] f32 | w2 [128] f32 | part[256] f32
#define SMEM1    (SM_MISC + 512 + 512 + 1024)

#define BAR_READY0 1
#define BAR_READY1 2
#define BAR_READY2 3
#define BAR_FREE0  4
#define BAR_FREE1  5
#define BAR_FREE2  6
#define BAR_CONS   7

// ---------------------------------------------------------------------------
// K1: logits = LeakyReLU(feat @ w1[0:128] + wgt*w1[128]) @ w2
// fp16 2-pass (A single fp16, W hi/lo fp16), warp-specialized, triple-buffered.
// Consumer warp tile: 32 rows x 64 cols.
// ---------------------------------------------------------------------------
extern "C" __global__ void __launch_bounds__(512, 1)
logits_kernel(const float* __restrict__ nbr,
              const float* __restrict__ wgt,
              const float* __restrict__ extra,
              const float* __restrict__ w1,
              const float* __restrict__ w2)
{
    extern __shared__ __align__(1024) char smem[];
    const int t    = threadIdx.x;
    const int lane = t & 31;
    const int w    = t >> 5;
    const uint32_t sb = smem_u32(smem);

    float* s_w1b = (float*)(smem + SM_MISC);
    float* s_w2  = s_w1b + 128;
    float* s_part = s_w2 + 128;      // [row*2 + wn]

    // ---- stage w1^T (Wt[n][k]) as fp16 hi/lo, swizzled (once) ----
    #pragma unroll 4
    for (int i = 0; i < 32; ++i) {
        int idx = t + i * 512;                 // 16384 = 128*128
        int n = idx >> 7, k = idx & 127;
        float x = w1[k * 128 + n];
        __half hx = __float2half_rn(x);
        __half lx = __float2half_rn(x - __half2float(hx));
        uint32_t off = sw_off(n, k >> 3) + (k & 7) * 2;
        asm volatile("st.shared.u16 [%0], %1;" :: "r"(sb + SM_WHI + off),
                     "h"(__half_as_ushort(hx)));
        asm volatile("st.shared.u16 [%0], %1;" :: "r"(sb + SM_WLO + off),
                     "h"(__half_as_ushort(lx)));
    }
    if (t < 128) { s_w1b[t] = w1[128 * 128 + t]; s_w2[t] = w2[t]; }
    __syncthreads();

    if (w >= 8) {
        // ================= PRODUCER (warps 8-15) =================
        const int pt = t & 255;
        const float4* nbr4   = (const float4*)nbr;
        const float4* extra4 = (const float4*)extra;
        int it = 0;
        for (int sup = blockIdx.x; sup < NSUP; sup += GRID1, ++it) {
            const int b = (it >= 3) ? (it % 3) : it;
            if (it >= 3) BAR_SYNC(BAR_FREE0 + b);
            const uint32_t aBuf = sb + SM_A0 + b * 32768;
            const int row0 = sup * 128;
            #pragma unroll 4
            for (int i = 0; i < 16; ++i) {
                int idx  = pt + i * 256;       // 4096 float4 = 128 rows x 32
                int row  = idx >> 5;
                int c4   = idx & 31;
                unsigned grow = (unsigned)(row0 + row);
                unsigned node = grow / KNB;
                float4 n = nbr4[(size_t)grow * 32 + c4];
                float4 e = extra4[(size_t)node * 32 + c4];
                float x0 = n.x * e.x, x1 = n.y * e.y, x2 = n.z * e.z, x3 = n.w * e.w;
                uint32_t p01, p23;
                asm("cvt.rn.f16x2.f32 %0, %1, %2;" : "=r"(p01) : "f"(x1), "f"(x0));
                asm("cvt.rn.f16x2.f32 %0, %1, %2;" : "=r"(p23) : "f"(x3), "f"(x2));
                uint32_t off = sw_off(row, c4 >> 1) + (c4 & 1) * 8;
                asm volatile("st.shared.v2.b32 [%0], {%1,%2};"
                             :: "r"(aBuf + off), "r"(p01), "r"(p23));
            }
            BAR_ARRIVE(BAR_READY0 + b);
        }
    } else {
        // ================= CONSUMER (warps 0-7) =================
        const int wm = w & 3;                  // row group: 32 rows
        const int wn = w >> 2;                 // col group: 64 cols
        const int aRow = wm * 32 + (lane & 15);
        const int aCb  = lane >> 4;
        const int aXor = aRow & 7;
        const int bNl  = ((lane >> 4) << 3) + (lane & 7);
        const int bCb  = (lane >> 3) & 1;
        const int bXor = lane & 7;
        const uint32_t nBase = (uint32_t)((wn * 64 + bNl) * 256);

        int it = 0;
        for (int sup = blockIdx.x; sup < NSUP; sup += GRID1, ++it) {
            const int b = (it >= 3) ? (it % 3) : it;
            BAR_SYNC(BAR_READY0 + b);
            const uint32_t aBase = sb + SM_A0 + b * 32768 + aRow * 256;
            const int row0 = sup * 128;

            float acc[2][8][4];
            #pragma unroll
            for (int mi = 0; mi < 2; ++mi)
                #pragma unroll
                for (int ni = 0; ni < 8; ++ni)
                    { acc[mi][ni][0]=acc[mi][ni][1]=acc[mi][ni][2]=acc[mi][ni][3]=0.f; }

            #pragma unroll
            for (int ks = 0; ks < 8; ++ks) {
                uint32_t a0[4], a1[4];
                uint32_t koffA = (uint32_t)(((2 * ks + aCb) ^ aXor) << 4);
                LDSM4(a0, aBase + koffA);
                LDSM4(a1, aBase + 4096 + koffA);
                uint32_t kc = (uint32_t)(((2 * ks + bCb) ^ bXor) << 4);
                #pragma unroll
                for (int j = 0; j < 4; ++j) {
                    uint32_t bh[4], bl[4];
                    uint32_t boff = nBase + (uint32_t)(j * 16 * 256) + kc;
                    LDSM4(bh, sb + SM_WHI + boff);
                    LDSM4(bl, sb + SM_WLO + boff);
                    MMA_F16(acc[0][2*j],   a0, bh);
                    MMA_F16(acc[0][2*j],   a0, bl);
                    MMA_F16(acc[0][2*j+1], a0, bh + 2);
                    MMA_F16(acc[0][2*j+1], a0, bl + 2);
                    MMA_F16(acc[1][2*j],   a1, bh);
                    MMA_F16(acc[1][2*j],   a1, bl);
                    MMA_F16(acc[1][2*j+1], a1, bh + 2);
                    MMA_F16(acc[1][2*j+1], a1, bl + 2);
                }
            }
            BAR_ARRIVE(BAR_FREE0 + b);

            // ---- epilogue: bias + leaky_relu + dot(w2); partial over 64 cols ----
            const int grp = lane >> 2, qid = lane & 3;
            #pragma unroll
            for (int mi = 0; mi < 2; ++mi) {
                const int rowA = wm * 32 + mi * 16 + grp;     // local row
                const float wrA = __ldg(&wgt[row0 + rowA]);
                const float wrB = __ldg(&wgt[row0 + rowA + 8]);
                float pa = 0.f, pb = 0.f;
                #pragma unroll
                for (int ni = 0; ni < 8; ++ni) {
                    int c = wn * 64 + ni * 8 + qid * 2;
                    float b0 = s_w1b[c], b1 = s_w1b[c + 1];
                    float u0 = s_w2[c],  u1 = s_w2[c + 1];
                    float v;
                    v = acc[mi][ni][0] + wrA * b0; v = (v >= 0.f) ? v : 0.2f * v; pa += v * u0;
                    v = acc[mi][ni][1] + wrA * b1; v = (v >= 0.f) ? v : 0.2f * v; pa += v * u1;
                    v = acc[mi][ni][2] + wrB * b0; v = (v >= 0.f) ? v : 0.2f * v; pb += v * u0;
                    v = acc[mi][ni][3] + wrB * b1; v = (v >= 0.f) ? v : 0.2f * v; pb += v * u1;
                }
                pa += __shfl_xor_sync(0xffffffffu, pa, 1);
                pa += __shfl_xor_sync(0xffffffffu, pa, 2);
                pb += __shfl_xor_sync(0xffffffffu, pb, 1);
                pb += __shfl_xor_sync(0xffffffffu, pb, 2);
                if (qid == 0) {
                    s_part[rowA * 2 + wn]       = pa;
                    s_part[(rowA + 8) * 2 + wn] = pb;
                }
            }
            BAR_SYNC_C(BAR_CONS);
            if (wn == 0) {
                const int row = wm * 32 + lane;
                g_logits[row0 + row] = s_part[row * 2] + s_part[row * 2 + 1];
            }
            BAR_SYNC_C(BAR_CONS);
        }
    }
}

// ---------------------------------------------------------------------------
// K2: softmax over K + weighted aggregation (memory bound)
// ---------------------------------------------------------------------------
extern "C" __global__ void __launch_bounds__(128, 8)
softmax_agg_kernel(const float* __restrict__ nbr)
{
    const int t = threadIdx.x, lane = t & 31, w = t >> 5;
    const long node = (long)blockIdx.x * 4 + w;

    float lg[KNB];
    float m = -1e30f;
    #pragma unroll
    for (int k = 0; k < KNB; ++k) { lg[k] = g_logits[node * KNB + k]; m = fmaxf(m, lg[k]); }
    float sum = 0.f;
    #pragma unroll
    for (int k = 0; k < KNB; ++k) { lg[k] = expf(lg[k] - m); sum += lg[k]; }
    const float inv = 1.0f / sum;

    const float4* nv = (const float4*)(nbr + node * KNB * DIM);
    float4 agg = make_float4(0.f, 0.f, 0.f, 0.f);
    #pragma unroll
    for (int k = 0; k < KNB; ++k) {
        float4 n4 = nv[k * 32 + lane];
        float pk = lg[k] * inv;
        agg.x += pk * n4.x; agg.y += pk * n4.y;
        agg.z += pk * n4.z; agg.w += pk * n4.w;
    }
    ((float4*)g_agg)[node * 32 + lane] = agg;
}

// ---------------------------------------------------------------------------
// K3: out = relu(concat(self, agg) @ w3), bf16 hi/lo 3-pass mma.sync.
// ---------------------------------------------------------------------------
#define SM3_WHI 0
#define SM3_WLO 65536
#define SM3_AHI 131072
#define SM3_ALO 163840
#define SMEM3   196608
#define NT3     (NODES / 128)      // 256 tiles

extern "C" __global__ void __launch_bounds__(256, 1)
out_gemm_kernel(const float* __restrict__ selfv,
                const float* __restrict__ w3,
                float* __restrict__ out)
{
    extern __shared__ __align__(1024) char smem[];
    const int t    = threadIdx.x;
    const int lane = t & 31;
    const int w    = t >> 5;
    const uint32_t sb = smem_u32(smem);

    // ---- stage w3^T (Wt[n][k], k=0..255) bf16 hi/lo, swizzled (once) ----
    #pragma unroll 4
    for (int i = 0; i < 128; ++i) {
        int idx = t + i * 256;                 // 32768 = 256*128
        int n = idx >> 8, k = idx & 255;
        float x = w3[k * 128 + n];
        uint16_t hx, lx;
        asm("cvt.rn.bf16.f32 %0, %1;" : "=h"(hx) : "f"(x));
        float hf = __uint_as_float(((uint32_t)hx) << 16);
        asm("cvt.rn.bf16.f32 %0, %1;" : "=h"(lx) : "f"(x - hf));
        uint32_t off = (uint32_t)(n * 512 + (((k >> 3) ^ (n & 7)) << 4) + (k & 7) * 2);
        asm volatile("st.shared.u16 [%0], %1;" :: "r"(sb + SM3_WHI + off), "h"(hx));
        asm volatile("st.shared.u16 [%0], %1;" :: "r"(sb + SM3_WLO + off), "h"(lx));
    }

    const int aRow = (w << 4) + (lane & 15);
    const int aCb  = lane >> 4;
    const int aXor = aRow & 7;
    const int bNl  = ((lane >> 4) << 3) + (lane & 7);
    const int bCb  = (lane >> 3) & 1;
    const uint32_t aHiBase = sb + SM3_AHI + aRow * 256;
    const uint32_t aLoBase = sb + SM3_ALO + aRow * 256;

    for (int tile = blockIdx.x; tile < NT3; tile += 128) {
        const int r0 = tile * 128;

        float acc[16][4];
        #pragma unroll
        for (int nt = 0; nt < 16; ++nt)
            { acc[nt][0] = acc[nt][1] = acc[nt][2] = acc[nt][3] = 0.f; }

        #pragma unroll 1
        for (int half = 0; half < 2; ++half) {
            __syncthreads();
            const float4* src = (const float4*)(half ? (const float*)g_agg : selfv);
            #pragma unroll 4
            for (int i = 0; i < 16; ++i) {
                int idx = t + i * 256;
                int row = idx >> 5;
                int c4  = idx & 31;
                float4 v = src[(size_t)(r0 + row) * 32 + c4];
                uint32_t h01, h23, l01, l23;
                split4(v.x, v.y, v.z, v.w, h01, h23, l01, l23);
                uint32_t off = sw_off(row, c4 >> 1) + (c4 & 1) * 8;
                asm volatile("st.shared.v2.b32 [%0], {%1,%2};"
                             :: "r"(sb + SM3_AHI + off), "r"(h01), "r"(h23));
                asm volatile("st.shared.v2.b32 [%0], {%1,%2};"
                             :: "r"(sb + SM3_ALO + off), "r"(l01), "r"(l23));
            }
            __syncthreads();

            #pragma unroll
            for (int ks = 0; ks < 8; ++ks) {
                uint32_t ah[4], al[4];
                uint32_t aoff = (uint32_t)(((2 * ks + aCb) ^ aXor) << 4);
                LDSM4(ah, aHiBase + aoff);
                LDSM4(al, aLoBase + aoff);
                const int kc = half * 16 + 2 * ks + bCb;
                #pragma unroll
                for (int j = 0; j < 8; ++j) {
                    int n = j * 16 + bNl;
                    uint32_t off = (uint32_t)(n * 512 + ((kc ^ (n & 7)) << 4));
                    uint32_t rh[4], rl[4];
                    LDSM4(rh, sb + SM3_WHI + off);
                    LDSM4(rl, sb + SM3_WLO + off);
                    MMA_BF16(acc[2*j],   ah, rh);
                    MMA_BF16(acc[2*j],   ah, rl);
                    MMA_BF16(acc[2*j],   al, rh);
                    MMA_BF16(acc[2*j+1], ah, rh + 2);
                    MMA_BF16(acc[2*j+1], ah, rl + 2);
                    MMA_BF16(acc[2*j+1], al, rh + 2);
                }
            }
        }

        const int grp = lane >> 2, qid = lane & 3;
        const int row0g = r0 + (w << 4) + grp;
        #pragma unroll
        for (int nt = 0; nt < 16; ++nt) {
            int col = nt * 8 + qid * 2;
            float2 o0, o1;
            o0.x = fmaxf(acc[nt][0], 0.f); o0.y = fmaxf(acc[nt][1], 0.f);
            o1.x = fmaxf(acc[nt][2], 0.f); o1.y = fmaxf(acc[nt][3], 0.f);
            *(float2*)(out + (size_t)row0g * 128 + col)       = o0;
            *(float2*)(out + (size_t)(row0g + 8) * 128 + col) = o1;
        }
    }
}

// ---------------------------------------------------------------------------
extern "C" void kernel_launch(void* const* d_in, const int* in_sizes, int n_in,
                              void* d_out, int out_size)
{
    int idx = 0;
    const float* selfv = (const float*)d_in[idx++];
    const float* nbr   = (const float*)d_in[idx++];
    if (idx < n_in && in_sizes[idx] == 1) idx++;   // batch_size scalar
    idx++;                                         // masks (unused)
    const float* wgt   = (const float*)d_in[idx++];
    const float* extra = (const float*)d_in[idx++];
    const float* w1    = (const float*)d_in[idx++];
    const float* w2    = (const float*)d_in[idx++];
    const float* w3    = (const float*)d_in[idx++];
    float* out = (float*)d_out;

    cudaFuncSetAttribute(logits_kernel,   cudaFuncAttributeMaxDynamicSharedMemorySize, SMEM1);
    cudaFuncSetAttribute(out_gemm_kernel, cudaFuncAttributeMaxDynamicSharedMemorySize, SMEM3);

    logits_kernel<<<GRID1, 512, SMEM1>>>(nbr, wgt, extra, w1, w2);
    softmax_agg_kernel<<<NODES / 4, 128>>>(nbr);
    out_gemm_kernel<<<128, 256, SMEM3>>>(selfv, w3, out);
    (void)out_size; (void)n_in;
}

// round 6
// speedup vs baseline: 2.2637x; 1.1003x over previous
#include <cuda_runtime.h>
#include <cuda_fp16.h>
#include <cstdint>

#define NODES 32768
#define KNB   12
#define DIM   128
#define ROWS  (NODES * KNB)          // 393216
#define NSUP  (ROWS / 128)           // 3072 row-tiles of 128
#define GRID1 152

__device__ float g_agg[NODES * DIM];
__device__ float g_logits[ROWS];

__device__ __forceinline__ uint32_t smem_u32(const void* p) {
    uint32_t a;
    asm("{ .reg .u64 t; cvta.to.shared.u64 t, %1; cvt.u32.u64 %0, t; }"
        : "=r"(a) : "l"(p));
    return a;
}

#define LDSM4(r, addr) \
    asm volatile("ldmatrix.sync.aligned.m8n8.x4.shared.b16 {%0,%1,%2,%3}, [%4];" \
        : "=r"((r)[0]), "=r"((r)[1]), "=r"((r)[2]), "=r"((r)[3]) : "r"(addr))

#define MMA_F16(acc, a, b) \
    asm volatile("mma.sync.aligned.m16n8k16.row.col.f32.f16.f16.f32 " \
        "{%0,%1,%2,%3}, {%4,%5,%6,%7}, {%8,%9}, {%0,%1,%2,%3};" \
        : "+f"((acc)[0]), "+f"((acc)[1]), "+f"((acc)[2]), "+f"((acc)[3]) \
        : "r"((a)[0]), "r"((a)[1]), "r"((a)[2]), "r"((a)[3]), \
          "r"((b)[0]), "r"((b)[1]))

#define BAR_SYNC(id)    asm volatile("bar.sync %0, 512;"   :: "r"(id) : "memory")
#define BAR_ARRIVE(id)  asm volatile("bar.arrive %0, 512;" :: "r"(id) : "memory")
#define BAR_SYNC_C(id)  asm volatile("bar.sync %0, 256;"   :: "r"(id) : "memory")

__device__ __forceinline__ uint32_t sw_off(int row, int chunk) {
    return (uint32_t)(row * 256 + ((chunk ^ (row & 7)) << 4));
}

// ---------------------------------------------------------------------------
// K1 SMEM layout. fp16 tiles, A rows 256B (128 fp16), 16B XOR swizzle.
#define SM_W     0                  // w1^T fp16 (32KB)
#define SM_A0    32768              // feat fp16 buffers (32KB each)
#define SM_A1    65536
#define SM_A2    98304
#define SM_MISC  131072             // w1 bias [128] f32 | w2 [128] f32 | part[256] f32
#define SMEM1    (SM_MISC + 512 + 512 + 1024)

#define BAR_READY0 1
#define BAR_READY1 2
#define BAR_READY2 3
#define BAR_FREE0  4
#define BAR_FREE1  5
#define BAR_FREE2  6
#define BAR_CONS   7

// ---------------------------------------------------------------------------
// K1: logits = LeakyReLU(feat @ w1[0:128] + wgt*w1[128]) @ w2
// Single-pass fp16 mma.sync, warp-specialized, triple-buffered.
// Consumer warp tile: 32 rows x 64 cols.
// ---------------------------------------------------------------------------
extern "C" __global__ void __launch_bounds__(512, 1)
logits_kernel(const float* __restrict__ nbr,
              const float* __restrict__ wgt,
              const float* __restrict__ extra,
              const float* __restrict__ w1,
              const float* __restrict__ w2)
{
    extern __shared__ __align__(1024) char smem[];
    const int t    = threadIdx.x;
    const int lane = t & 31;
    const int w    = t >> 5;
    const uint32_t sb = smem_u32(smem);

    float* s_w1b  = (float*)(smem + SM_MISC);
    float* s_w2   = s_w1b + 128;
    float* s_part = s_w2 + 128;      // [row*2 + wn]

    // ---- stage w1^T (Wt[n][k]) as fp16, swizzled (once) ----
    #pragma unroll 4
    for (int i = 0; i < 32; ++i) {
        int idx = t + i * 512;                 // 16384 = 128*128
        int n = idx >> 7, k = idx & 127;
        __half hx = __float2half_rn(w1[k * 128 + n]);
        uint32_t off = sw_off(n, k >> 3) + (k & 7) * 2;
        asm volatile("st.shared.u16 [%0], %1;" :: "r"(sb + SM_W + off),
                     "h"(__half_as_ushort(hx)));
    }
    if (t < 128) { s_w1b[t] = w1[128 * 128 + t]; s_w2[t] = w2[t]; }
    __syncthreads();

    if (w >= 8) {
        // ================= PRODUCER (warps 8-15) =================
        const int pt = t & 255;
        const float4* nbr4   = (const float4*)nbr;
        const float4* extra4 = (const float4*)extra;
        int it = 0;
        for (int sup = blockIdx.x; sup < NSUP; sup += GRID1, ++it) {
            const int b = (it >= 3) ? (it % 3) : it;
            if (it >= 3) BAR_SYNC(BAR_FREE0 + b);
            const uint32_t aBuf = sb + SM_A0 + b * 32768;
            const int row0 = sup * 128;
            #pragma unroll 4
            for (int i = 0; i < 16; ++i) {
                int idx  = pt + i * 256;       // 4096 float4 = 128 rows x 32
                int row  = idx >> 5;
                int c4   = idx & 31;
                unsigned grow = (unsigned)(row0 + row);
                unsigned node = grow / KNB;
                float4 n = nbr4[(size_t)grow * 32 + c4];
                float4 e = extra4[(size_t)node * 32 + c4];
                float x0 = n.x * e.x, x1 = n.y * e.y, x2 = n.z * e.z, x3 = n.w * e.w;
                uint32_t p01, p23;
                asm("cvt.rn.f16x2.f32 %0, %1, %2;" : "=r"(p01) : "f"(x1), "f"(x0));
                asm("cvt.rn.f16x2.f32 %0, %1, %2;" : "=r"(p23) : "f"(x3), "f"(x2));
                uint32_t off = sw_off(row, c4 >> 1) + (c4 & 1) * 8;
                asm volatile("st.shared.v2.b32 [%0], {%1,%2};"
                             :: "r"(aBuf + off), "r"(p01), "r"(p23));
            }
            BAR_ARRIVE(BAR_READY0 + b);
        }
    } else {
        // ================= CONSUMER (warps 0-7) =================
        const int wm = w & 3;                  // row group: 32 rows
        const int wn = w >> 2;                 // col group: 64 cols
        const int aRow = wm * 32 + (lane & 15);
        const int aCb  = lane >> 4;
        const int aXor = aRow & 7;
        const int bNl  = ((lane >> 4) << 3) + (lane & 7);
        const int bCb  = (lane >> 3) & 1;
        const int bXor = lane & 7;
        const uint32_t nBase = (uint32_t)((wn * 64 + bNl) * 256);

        int it = 0;
        for (int sup = blockIdx.x; sup < NSUP; sup += GRID1, ++it) {
            const int b = (it >= 3) ? (it % 3) : it;
            BAR_SYNC(BAR_READY0 + b);
            const uint32_t aBase = sb + SM_A0 + b * 32768 + aRow * 256;
            const int row0 = sup * 128;

            float acc[2][8][4];
            #pragma unroll
            for (int mi = 0; mi < 2; ++mi)
                #pragma unroll
                for (int ni = 0; ni < 8; ++ni)
                    { acc[mi][ni][0]=acc[mi][ni][1]=acc[mi][ni][2]=acc[mi][ni][3]=0.f; }

            #pragma unroll
            for (int ks = 0; ks < 8; ++ks) {
                uint32_t a0[4], a1[4];
                uint32_t koffA = (uint32_t)(((2 * ks + aCb) ^ aXor) << 4);
                LDSM4(a0, aBase + koffA);
                LDSM4(a1, aBase + 4096 + koffA);
                uint32_t kc = (uint32_t)(((2 * ks + bCb) ^ bXor) << 4);
                #pragma unroll
                for (int j = 0; j < 4; ++j) {
                    uint32_t bh[4];
                    LDSM4(bh, sb + SM_W + nBase + (uint32_t)(j * 16 * 256) + kc);
                    MMA_F16(acc[0][2*j],   a0, bh);
                    MMA_F16(acc[0][2*j+1], a0, bh + 2);
                    MMA_F16(acc[1][2*j],   a1, bh);
                    MMA_F16(acc[1][2*j+1], a1, bh + 2);
                }
            }
            BAR_ARRIVE(BAR_FREE0 + b);

            // ---- epilogue: bias + leaky_relu + dot(w2); partial over 64 cols ----
            const int grp = lane >> 2, qid = lane & 3;
            #pragma unroll
            for (int mi = 0; mi < 2; ++mi) {
                const int rowA = wm * 32 + mi * 16 + grp;     // local row
                const float wrA = __ldg(&wgt[row0 + rowA]);
                const float wrB = __ldg(&wgt[row0 + rowA + 8]);
                float pa = 0.f, pb = 0.f;
                #pragma unroll
                for (int ni = 0; ni < 8; ++ni) {
                    int c = wn * 64 + ni * 8 + qid * 2;
                    float b0 = s_w1b[c], b1 = s_w1b[c + 1];
                    float u0 = s_w2[c],  u1 = s_w2[c + 1];
                    float v;
                    v = acc[mi][ni][0] + wrA * b0; v = (v >= 0.f) ? v : 0.2f * v; pa += v * u0;
                    v = acc[mi][ni][1] + wrA * b1; v = (v >= 0.f) ? v : 0.2f * v; pa += v * u1;
                    v = acc[mi][ni][2] + wrB * b0; v = (v >= 0.f) ? v : 0.2f * v; pb += v * u0;
                    v = acc[mi][ni][3] + wrB * b1; v = (v >= 0.f) ? v : 0.2f * v; pb += v * u1;
                }
                pa += __shfl_xor_sync(0xffffffffu, pa, 1);
                pa += __shfl_xor_sync(0xffffffffu, pa, 2);
                pb += __shfl_xor_sync(0xffffffffu, pb, 1);
                pb += __shfl_xor_sync(0xffffffffu, pb, 2);
                if (qid == 0) {
                    s_part[rowA * 2 + wn]       = pa;
                    s_part[(rowA + 8) * 2 + wn] = pb;
                }
            }
            BAR_SYNC_C(BAR_CONS);
            if (wn == 0) {
                const int row = wm * 32 + lane;
                g_logits[row0 + row] = s_part[row * 2] + s_part[row * 2 + 1];
            }
            BAR_SYNC_C(BAR_CONS);
        }
    }
}

// ---------------------------------------------------------------------------
// K2: softmax over K + weighted aggregation (memory bound)
// ---------------------------------------------------------------------------
extern "C" __global__ void __launch_bounds__(128, 8)
softmax_agg_kernel(const float* __restrict__ nbr)
{
    const int t = threadIdx.x, lane = t & 31, w = t >> 5;
    const long node = (long)blockIdx.x * 4 + w;

    float lg[KNB];
    float m = -1e30f;
    #pragma unroll
    for (int k = 0; k < KNB; ++k) { lg[k] = g_logits[node * KNB + k]; m = fmaxf(m, lg[k]); }
    float sum = 0.f;
    #pragma unroll
    for (int k = 0; k < KNB; ++k) { lg[k] = expf(lg[k] - m); sum += lg[k]; }
    const float inv = 1.0f / sum;

    const float4* nv = (const float4*)(nbr + node * KNB * DIM);
    float4 agg = make_float4(0.f, 0.f, 0.f, 0.f);
    #pragma unroll
    for (int k = 0; k < KNB; ++k) {
        float4 n4 = nv[k * 32 + lane];
        float pk = lg[k] * inv;
        agg.x += pk * n4.x; agg.y += pk * n4.y;
        agg.z += pk * n4.z; agg.w += pk * n4.w;
    }
    ((float4*)g_agg)[node * 32 + lane] = agg;
}

// ---------------------------------------------------------------------------
// K3: out = relu(concat(self, agg) @ w3), single-pass fp16 mma.sync.
// Warp tile 32 rows x 64 cols; A in two K-halves through one 32KB buffer.
// W3^T rows: 512B (256 fp16 k), A rows: 256B.
// ---------------------------------------------------------------------------
#define SM3_W   0                  // w3^T fp16 (64KB)
#define SM3_A   65536              // A fp16 staging (32KB)
#define SMEM3   (65536 + 32768)
#define NT3     (NODES / 128)      // 256 tiles

extern "C" __global__ void __launch_bounds__(256, 1)
out_gemm_kernel(const float* __restrict__ selfv,
                const float* __restrict__ w3,
                float* __restrict__ out)
{
    extern __shared__ __align__(1024) char smem[];
    const int t    = threadIdx.x;
    const int lane = t & 31;
    const int w    = t >> 5;
    const uint32_t sb = smem_u32(smem);

    // ---- stage w3^T (Wt[n][k], k=0..255) fp16, swizzled (once) ----
    #pragma unroll 4
    for (int i = 0; i < 128; ++i) {
        int idx = t + i * 256;                 // 32768 = 256*128
        int n = idx >> 8, k = idx & 255;
        __half hx = __float2half_rn(w3[k * 128 + n]);
        uint32_t off = (uint32_t)(n * 512 + (((k >> 3) ^ (n & 7)) << 4) + (k & 7) * 2);
        asm volatile("st.shared.u16 [%0], %1;" :: "r"(sb + SM3_W + off),
                     "h"(__half_as_ushort(hx)));
    }

    const int wm = w & 3;
    const int wn = w >> 2;
    const int aRow = wm * 32 + (lane & 15);
    const int aCb  = lane >> 4;
    const int aXor = aRow & 7;
    const int bNl  = ((lane >> 4) << 3) + (lane & 7);
    const int bCb  = (lane >> 3) & 1;
    const int bXor = lane & 7;
    const uint32_t nBase = (uint32_t)((wn * 64 + bNl) * 512);
    const uint32_t aBase = sb + SM3_A + aRow * 256;

    for (int tile = blockIdx.x; tile < NT3; tile += 128) {
        const int r0 = tile * 128;

        float acc[2][8][4];
        #pragma unroll
        for (int mi = 0; mi < 2; ++mi)
            #pragma unroll
            for (int ni = 0; ni < 8; ++ni)
                { acc[mi][ni][0]=acc[mi][ni][1]=acc[mi][ni][2]=acc[mi][ni][3]=0.f; }

        #pragma unroll 1
        for (int half = 0; half < 2; ++half) {
            __syncthreads();
            const float4* src = (const float4*)(half ? (const float*)g_agg : selfv);
            #pragma unroll 4
            for (int i = 0; i < 16; ++i) {
                int idx = t + i * 256;         // 4096 float4
                int row = idx >> 5;
                int c4  = idx & 31;
                float4 v = src[(size_t)(r0 + row) * 32 + c4];
                uint32_t p01, p23;
                asm("cvt.rn.f16x2.f32 %0, %1, %2;" : "=r"(p01) : "f"(v.y), "f"(v.x));
                asm("cvt.rn.f16x2.f32 %0, %1, %2;" : "=r"(p23) : "f"(v.w), "f"(v.z));
                uint32_t off = sw_off(row, c4 >> 1) + (c4 & 1) * 8;
                asm volatile("st.shared.v2.b32 [%0], {%1,%2};"
                             :: "r"(sb + SM3_A + off), "r"(p01), "r"(p23));
            }
            __syncthreads();

            #pragma unroll
            for (int ks = 0; ks < 8; ++ks) {
                uint32_t a0[4], a1[4];
                uint32_t koffA = (uint32_t)(((2 * ks + aCb) ^ aXor) << 4);
                LDSM4(a0, aBase + koffA);
                LDSM4(a1, aBase + 4096 + koffA);
                const uint32_t kc = (uint32_t)(((half * 16 + 2 * ks + bCb) ^ bXor) << 4);
                #pragma unroll
                for (int j = 0; j < 4; ++j) {
                    uint32_t bh[4];
                    LDSM4(bh, sb + SM3_W + nBase + (uint32_t)(j * 16 * 512) + kc);
                    MMA_F16(acc[0][2*j],   a0, bh);
                    MMA_F16(acc[0][2*j+1], a0, bh + 2);
                    MMA_F16(acc[1][2*j],   a1, bh);
                    MMA_F16(acc[1][2*j+1], a1, bh + 2);
                }
            }
        }

        // ---- relu + store ----
        const int grp = lane >> 2, qid = lane & 3;
        #pragma unroll
        for (int mi = 0; mi < 2; ++mi) {
            const int rowg = r0 + wm * 32 + mi * 16 + grp;
            #pragma unroll
            for (int ni = 0; ni < 8; ++ni) {
                int col = wn * 64 + ni * 8 + qid * 2;
                float2 o0, o1;
                o0.x = fmaxf(acc[mi][ni][0], 0.f); o0.y = fmaxf(acc[mi][ni][1], 0.f);
                o1.x = fmaxf(acc[mi][ni][2], 0.f); o1.y = fmaxf(acc[mi][ni][3], 0.f);
                *(float2*)(out + (size_t)rowg * 128 + col)       = o0;
                *(float2*)(out + (size_t)(rowg + 8) * 128 + col) = o1;
            }
        }
    }
}

// ---------------------------------------------------------------------------
extern "C" void kernel_launch(void* const* d_in, const int* in_sizes, int n_in,
                              void* d_out, int out_size)
{
    int idx = 0;
    const float* selfv = (const float*)d_in[idx++];
    const float* nbr   = (const float*)d_in[idx++];
    if (idx < n_in && in_sizes[idx] == 1) idx++;   // batch_size scalar
    idx++;                                         // masks (unused)
    const float* wgt   = (const float*)d_in[idx++];
    const float* extra = (const float*)d_in[idx++];
    const float* w1    = (const float*)d_in[idx++];
    const float* w2    = (const float*)d_in[idx++];
    const float* w3    = (const float*)d_in[idx++];
    float* out = (float*)d_out;

    cudaFuncSetAttribute(logits_kernel,   cudaFuncAttributeMaxDynamicSharedMemorySize, SMEM1);
    cudaFuncSetAttribute(out_gemm_kernel, cudaFuncAttributeMaxDynamicSharedMemorySize, SMEM3);

    logits_kernel<<<GRID1, 512, SMEM1>>>(nbr, wgt, extra, w1, w2);
    softmax_agg_kernel<<<NODES / 4, 128>>>(nbr);
    out_gemm_kernel<<<128, 256, SMEM3>>>(selfv, w3, out);
    (void)out_size; (void)n_in;
}